// round 7
// baseline (speedup 1.0000x reference)
#include <cuda_runtime.h>
#include <math.h>

#define TT 50
#define HH 256
#define NCTA 16
#define NW 16
#define THREADS 512
#define NMBAR (2 * TT)

// scratch (no allocations allowed)
__device__ float g_feat[TT * 256];
__device__ float g_pre[TT * 768];
__device__ float g_lout[TT * HH];

__device__ __forceinline__ float eluf(float x) { return x > 0.f ? x : expm1f(x); }
__device__ __forceinline__ float sigm(float x) { return 1.f / (1.f + expf(-x)); }
// fast versions (recurrence only; ~1e-6 rel err, margin is 1e-3)
__device__ __forceinline__ float sigmfast(float x) {
    return __fdividef(1.f, 1.f + __expf(-x));
}
__device__ __forceinline__ float tanhfast(float x) {
    return __fdividef(2.f, 1.f + __expf(-2.f * x)) - 1.f;
}

__device__ __forceinline__ float warp_sum(float v) {
#pragma unroll
    for (int m = 16; m; m >>= 1) v += __shfl_xor_sync(0xffffffffu, v, m);
    return v;
}

__device__ __forceinline__ void st_cluster(const float* p, int rank, float v) {
    unsigned a = (unsigned)__cvta_generic_to_shared(p);
    unsigned r;
    asm("mapa.shared::cluster.u32 %0, %1, %2;" : "=r"(r) : "r"(a), "r"(rank));
    asm volatile("st.shared::cluster.f32 [%0], %1;" :: "r"(r), "f"(v) : "memory");
}

__device__ __forceinline__ void arrive_cluster_rel(unsigned local_mbar, int rank) {
    unsigned r;
    asm("mapa.shared::cluster.u32 %0, %1, %2;" : "=r"(r) : "r"(local_mbar), "r"(rank));
    asm volatile("mbarrier.arrive.release.cluster.shared::cluster.b64 _, [%0];"
                 :: "r"(r) : "memory");
}

// cta-scope acquire wait: data was written remotely INTO our own smem, so
// cta acquire is sufficient for visibility (matches production helper).
__device__ __forceinline__ void waitc(unsigned mbar) {
    asm volatile(
        "{\n\t"
        ".reg .pred P;\n\t"
        "WL%=:\n\t"
        "mbarrier.try_wait.parity.acquire.cta.shared::cta.b64 P, [%0], 0, 0x989680;\n\t"
        "@!P bra WL%=;\n\t"
        "}"
        :: "r"(mbar) : "memory");
}

__device__ __forceinline__ float dot8(float4 wa, float4 wb, float4 xa, float4 xb) {
    return wa.x*xa.x + wa.y*xa.y + wa.z*xa.z + wa.w*xa.w
         + wb.x*xb.x + wb.y*xb.y + wb.z*xb.z + wb.w*xb.w;
}

// ---------------------------------------------------------------------------
// feat: g_feat[t][0:128]  = elu(v0[t] @ W1v.T + b1v)   (warp-per-output)
//       g_feat[t][128:256]= elu(m0[t] @ W1m.T + b1m)
// ---------------------------------------------------------------------------
__global__ void feat_kernel(const float* __restrict__ v0, const float* __restrict__ m0,
                            const float* __restrict__ W1v, const float* __restrict__ b1v,
                            const float* __restrict__ W1m, const float* __restrict__ b1m)
{
    int t = blockIdx.x, by = blockIdx.y;
    int w = threadIdx.x >> 5, l = threadIdx.x & 31;
    if (by < 16) {
        int o = by * 8 + w;                    // 0..127
        const float* vr = v0 + t * 768;
        const float* wr = W1v + o * 768;
        float acc = 0.f;
#pragma unroll
        for (int c = 0; c < 6; c++) {
            float4 a = *(const float4*)(vr + c * 128 + 4 * l);
            float4 b = *(const float4*)(wr + c * 128 + 4 * l);
            acc += a.x*b.x + a.y*b.y + a.z*b.z + a.w*b.w;
        }
        acc = warp_sum(acc);
        if (l == 0) g_feat[t * 256 + o] = eluf(acc + b1v[o]);
    } else {
        int f = threadIdx.x;
        if (f < 128) {
            float acc = b1m[f] + m0[t * 2] * W1m[f * 2] + m0[t * 2 + 1] * W1m[f * 2 + 1];
            g_feat[t * 256 + 128 + f] = eluf(acc);
        }
    }
}

// ---------------------------------------------------------------------------
// pre2: g_pre[t][j] = Wih_low[j, :256] @ g_feat[t] + bih_low[j]
//                     + (bhh_low[j] for j<512)           (warp-per-output)
// ---------------------------------------------------------------------------
__global__ void pre2_kernel(const float* __restrict__ Wih_low,
                            const float* __restrict__ bih_low,
                            const float* __restrict__ bhh_low)
{
    int t = blockIdx.x;
    int w = threadIdx.x >> 5, l = threadIdx.x & 31;
    int o = blockIdx.y * 8 + w;                // 0..767
    const float* xr = g_feat + t * 256;
    const float* wr = Wih_low + o * 512;
    float4 a0 = *(const float4*)(xr + 4 * l);
    float4 a1 = *(const float4*)(xr + 128 + 4 * l);
    float4 b0 = *(const float4*)(wr + 4 * l);
    float4 b1 = *(const float4*)(wr + 128 + 4 * l);
    float acc = warp_sum(dot8(b0, b1, a0, a1));
    if (l == 0)
        g_pre[t * 768 + o] = acc + bih_low[o] + (o < 512 ? bhh_low[o] : 0.f);
}

// ---------------------------------------------------------------------------
// Recurrent kernel: persistent 16-CTA cluster, one hidden unit per warp.
// Smem: W_lh2 (= Wih_low[:,256:512]) + Wih_high. Regs: Whh_low, Whh_high.
// Exchange: each warp scatters its h scalar to all 16 ranks the moment it is
// ready (lanes 0-15, one rank each); __syncthreads; warp0 lanes issue 16
// release-arrives on the per-phase one-shot mbarrier (count=16). Consumers
// do a cta-scope acquire try_wait.
// ---------------------------------------------------------------------------
__global__ void __launch_bounds__(THREADS, 1) gru_kernel(
    const float* __restrict__ Wih_low, const float* __restrict__ Whh_low,
    const float* __restrict__ bhh_low,
    const float* __restrict__ Wih_high, const float* __restrict__ Whh_high,
    const float* __restrict__ bih_high, const float* __restrict__ bhh_high)
{
    extern __shared__ float smem[];
    float* sW  = smem;                       // [NW][2 mats][3 rows][256]  = 24576 floats
    float* sH1 = smem + NW * 1536;           // [2][256] double-buffered
    float* sH2 = sH1 + 512;                  // [2][256]

    const int tid = threadIdx.x;
    const int w = tid >> 5, l = tid & 31;
    unsigned rank;
    asm("mov.u32 %0, %%cluster_ctarank;" : "=r"(rank));
    const int i = (int)rank * NW + w;        // global hidden index 0..255
    const int c0 = 4 * l, c1 = 128 + 4 * l;
    float* wb = sW + w * 1536;

    const unsigned sm_base = (unsigned)__cvta_generic_to_shared(smem);
    const unsigned mb0 = sm_base + (NW * 1536 + 512 + 512) * 4;  // mbar array base

    sH1[tid] = 0.f;                          // both parities (512 floats each arr)
    sH2[tid] = 0.f;
    if (tid == 0) {
#pragma unroll 4
        for (int k = 0; k < NMBAR; k++)
            asm volatile("mbarrier.init.shared.b64 [%0], %1;"
                         :: "r"(mb0 + 8u * k), "r"(NCTA) : "memory");
    }

    const int j0 = i, j1 = 256 + i, j2 = 512 + i;
    const int jj[3] = { j0, j1, j2 };

    float4 wlh[3][2], whh[3][2];
#pragma unroll
    for (int g = 0; g < 3; g++) {
        int j = jj[g];
        *(float4*)(wb + g * 256 + c0)       = *(const float4*)(Wih_low + j * 512 + 256 + c0);
        *(float4*)(wb + g * 256 + c1)       = *(const float4*)(Wih_low + j * 512 + 256 + c1);
        *(float4*)(wb + 768 + g * 256 + c0) = *(const float4*)(Wih_high + j * 256 + c0);
        *(float4*)(wb + 768 + g * 256 + c1) = *(const float4*)(Wih_high + j * 256 + c1);
        wlh[g][0] = *(const float4*)(Whh_low + j * 256 + c0);
        wlh[g][1] = *(const float4*)(Whh_low + j * 256 + c1);
        whh[g][0] = *(const float4*)(Whh_high + j * 256 + c0);
        whh[g][1] = *(const float4*)(Whh_high + j * 256 + c1);
    }

    const float bLn = bhh_low[512 + i];                      // gh_n bias (low)
    const float cAr = bih_high[i] + bhh_high[i];             // high r: both biases fold
    const float cAz = bih_high[256 + i] + bhh_high[256 + i]; // high z
    const float cAn = bih_high[512 + i];                     // high n: gi bias
    const float cBn = bhh_high[512 + i];                     // high n: gh bias

    __syncthreads();
    // publish mbarrier inits + zeroed buffers cluster-wide (one-time)
    asm volatile("barrier.cluster.arrive.aligned;" ::: "memory");
    asm volatile("barrier.cluster.wait.aligned;" ::: "memory");

    float h1prev = 0.f, h2prev = 0.f;
    float Blr = 0.f, Blz = 0.f, Bln = 0.f;   // Whh_low @ h1(-1) = 0
    float pr = g_pre[j0], pz = g_pre[j1], pn = g_pre[j2];

    for (int t = 0; t < TT; t++) {
        const int p = t & 1;
        // ================= phase 1: low GRU (produce h1(t)) ==========
        if (t > 0) waitc(mb0 + 8u * (2 * t - 1));     // h2(t-1) arrivals
        float4 h2a = *(const float4*)(sH2 + (p ^ 1) * 256 + c0);
        float4 h2b = *(const float4*)(sH2 + (p ^ 1) * 256 + c1);
        float A0, A1, A2v;
        {
            float4 wa0 = *(const float4*)(wb + 0 * 256 + c0);
            float4 wb0 = *(const float4*)(wb + 0 * 256 + c1);
            float4 wa1 = *(const float4*)(wb + 1 * 256 + c0);
            float4 wb1 = *(const float4*)(wb + 1 * 256 + c1);
            float4 wa2 = *(const float4*)(wb + 2 * 256 + c0);
            float4 wb2 = *(const float4*)(wb + 2 * 256 + c1);
            A0 = dot8(wa0, wb0, h2a, h2b);
            A1 = dot8(wa1, wb1, h2a, h2b);
            A2v = dot8(wa2, wb2, h2a, h2b);
        }
        float Ar = warp_sum(A0), Az = warp_sum(A1), An = warp_sum(A2v);
        float r = sigmfast(pr + Ar + Blr);
        float z = sigmfast(pz + Az + Blz);
        float n = tanhfast(pn + An + r * (Bln + bLn));
        float h1n = (1.f - z) * n + z * h1prev;
        h1prev = h1n;

        // scatter h1(t) to all ranks immediately (transit overlaps stragglers)
        if (l < NCTA) st_cluster(sH1 + p * 256 + i, l, h1n);
        if (l == 16) g_lout[t * 256 + i] = h1n;       // off critical path
        __syncthreads();
        if (w == 0 && l < NCTA)
            arrive_cluster_rel(mb0 + 8u * (2 * t), l);

        // hidden work (overlaps DSMEM transit): B_high = Whh_high @ h2(t-1)
        float Bhr = warp_sum(dot8(whh[0][0], whh[0][1], h2a, h2b));
        float Bhz = warp_sum(dot8(whh[1][0], whh[1][1], h2a, h2b));
        float Bhn = warp_sum(dot8(whh[2][0], whh[2][1], h2a, h2b));
        // prefetch next step's pre-activations early
        if (t + 1 < TT) {
            pr = __ldg(g_pre + (t + 1) * 768 + j0);
            pz = __ldg(g_pre + (t + 1) * 768 + j1);
            pn = __ldg(g_pre + (t + 1) * 768 + j2);
        }

        waitc(mb0 + 8u * (2 * t));                    // h1(t) arrivals
        float4 h1a = *(const float4*)(sH1 + p * 256 + c0);
        float4 h1b = *(const float4*)(sH1 + p * 256 + c1);

        // ================= phase 2: high GRU (produce h2(t)) =========
        float G0, G1, G2;
        {
            float4 wa0 = *(const float4*)(wb + 768 + 0 * 256 + c0);
            float4 wb0 = *(const float4*)(wb + 768 + 0 * 256 + c1);
            float4 wa1 = *(const float4*)(wb + 768 + 1 * 256 + c0);
            float4 wb1 = *(const float4*)(wb + 768 + 1 * 256 + c1);
            float4 wa2 = *(const float4*)(wb + 768 + 2 * 256 + c0);
            float4 wb2 = *(const float4*)(wb + 768 + 2 * 256 + c1);
            G0 = dot8(wa0, wb0, h1a, h1b);
            G1 = dot8(wa1, wb1, h1a, h1b);
            G2 = dot8(wa2, wb2, h1a, h1b);
        }
        float A2r = warp_sum(G0), A2z = warp_sum(G1), A2n = warp_sum(G2);
        float r2 = sigmfast(cAr + A2r + Bhr);
        float z2 = sigmfast(cAz + A2z + Bhz);
        float n2 = tanhfast(cAn + A2n + r2 * (Bhn + cBn));
        float h2n = (1.f - z2) * n2 + z2 * h2prev;
        h2prev = h2n;

        if (l < NCTA) st_cluster(sH2 + p * 256 + i, l, h2n);
        __syncthreads();
        if (w == 0 && l < NCTA)
            arrive_cluster_rel(mb0 + 8u * (2 * t + 1), l);

        // hidden work: next step's B_low = Whh_low @ h1(t)
        Blr = warp_sum(dot8(wlh[0][0], wlh[0][1], h1a, h1b));
        Blz = warp_sum(dot8(wlh[1][0], wlh[1][1], h1a, h1b));
        Bln = warp_sum(dot8(wlh[2][0], wlh[2][1], h1a, h1b));
    }
    // trailing cluster sync: no CTA exits while peers' DSMEM ops may target it
    asm volatile("barrier.cluster.arrive.aligned;" ::: "memory");
    asm volatile("barrier.cluster.wait.aligned;" ::: "memory");
}

// ---------------------------------------------------------------------------
// Post-kernel (warp-per-output):
//   v_n[t][o] = sigmoid(elu(h1[t][0:128]) . W2v[o] + b2v[o])
//   m_n[t][o] = tanh   (elu(h1[t][128:256]) . W2m[o] + b2m[o])
// ---------------------------------------------------------------------------
__global__ void post_kernel(const float* __restrict__ W2v, const float* __restrict__ b2v,
                            const float* __restrict__ W2m, const float* __restrict__ b2m,
                            float* __restrict__ out)
{
    int t = blockIdx.x, by = blockIdx.y;
    int w = threadIdx.x >> 5, l = threadIdx.x & 31;
    if (by < 12) {
        float4 h = *(const float4*)(g_lout + t * 256 + 4 * l);
        h.x = eluf(h.x); h.y = eluf(h.y); h.z = eluf(h.z); h.w = eluf(h.w);
#pragma unroll
        for (int q = 0; q < 8; q++) {
            int o = by * 64 + w * 8 + q;
            float4 b = *(const float4*)(W2v + o * 128 + 4 * l);
            float acc = warp_sum(h.x*b.x + h.y*b.y + h.z*b.z + h.w*b.w);
            if (l == 0) out[t * 768 + o] = sigm(acc + b2v[o]);
        }
    } else if (w < 2) {
        float4 h = *(const float4*)(g_lout + t * 256 + 128 + 4 * l);
        h.x = eluf(h.x); h.y = eluf(h.y); h.z = eluf(h.z); h.w = eluf(h.w);
        float4 b = *(const float4*)(W2m + w * 128 + 4 * l);
        float acc = warp_sum(h.x*b.x + h.y*b.y + h.z*b.z + h.w*b.w);
        if (l == 0) out[TT * 768 + t * 2 + w] = tanhf(acc + b2m[w]);
    }
}

// ---------------------------------------------------------------------------
extern "C" void kernel_launch(void* const* d_in, const int* in_sizes, int n_in,
                              void* d_out, int out_size) {
    const float* v0       = (const float*)d_in[0];
    const float* m0       = (const float*)d_in[1];
    const float* W1v      = (const float*)d_in[2];
    const float* b1v      = (const float*)d_in[3];
    const float* W1m      = (const float*)d_in[4];
    const float* b1m      = (const float*)d_in[5];
    const float* Wih_low  = (const float*)d_in[6];
    const float* Whh_low  = (const float*)d_in[7];
    const float* bih_low  = (const float*)d_in[8];
    const float* bhh_low  = (const float*)d_in[9];
    const float* Wih_high = (const float*)d_in[10];
    const float* Whh_high = (const float*)d_in[11];
    const float* bih_high = (const float*)d_in[12];
    const float* bhh_high = (const float*)d_in[13];
    const float* W2v      = (const float*)d_in[14];
    const float* b2v      = (const float*)d_in[15];
    const float* W2m      = (const float*)d_in[16];
    const float* b2m      = (const float*)d_in[17];
    float* out = (float*)d_out;

    feat_kernel<<<dim3(TT, 17), 256>>>(v0, m0, W1v, b1v, W1m, b1m);
    pre2_kernel<<<dim3(TT, 96), 256>>>(Wih_low, bih_low, bhh_low);

    // smem: weights 24576 + h1 512 + h2 512 floats, + 100 mbars
    const int SMEM = (NW * 1536 + 512 + 512) * (int)sizeof(float) + NMBAR * 8;
    cudaFuncSetAttribute(gru_kernel, cudaFuncAttributeMaxDynamicSharedMemorySize, SMEM);
    cudaFuncSetAttribute(gru_kernel, cudaFuncAttributeNonPortableClusterSizeAllowed, 1);

    cudaLaunchConfig_t cfg = {};
    cfg.gridDim = dim3(NCTA, 1, 1);
    cfg.blockDim = dim3(THREADS, 1, 1);
    cfg.dynamicSmemBytes = SMEM;
    cfg.stream = 0;
    cudaLaunchAttribute attr[1];
    attr[0].id = cudaLaunchAttributeClusterDimension;
    attr[0].val.clusterDim.x = NCTA;
    attr[0].val.clusterDim.y = 1;
    attr[0].val.clusterDim.z = 1;
    cfg.attrs = attr;
    cfg.numAttrs = 1;
    cudaLaunchKernelEx(&cfg, gru_kernel, Wih_low, Whh_low, bhh_low,
                       Wih_high, Whh_high, bih_high, bhh_high);

    post_kernel<<<dim3(TT, 13), 256>>>(W2v, b2v, W2m, b2m, out);
}

// round 8
// speedup vs baseline: 1.2875x; 1.2875x over previous
#include <cuda_runtime.h>
#include <math.h>

#define TT 50
#define HH 256
#define NCTA 16
#define NW 16
#define THREADS 512
#define NMBAR (2 * TT)

// scratch (no allocations allowed)
__device__ float g_feat[TT * 256];
__device__ float g_pre[TT * 768];
__device__ float g_lout[TT * HH];

__device__ __forceinline__ float eluf(float x) { return x > 0.f ? x : expm1f(x); }
__device__ __forceinline__ float sigm(float x) { return 1.f / (1.f + expf(-x)); }
// fast versions (recurrence only; ~1e-6 rel err, margin is 1e-3)
__device__ __forceinline__ float sigmfast(float x) {
    return __fdividef(1.f, 1.f + __expf(-x));
}
__device__ __forceinline__ float tanhfast(float x) {
    return __fdividef(2.f, 1.f + __expf(-2.f * x)) - 1.f;
}

__device__ __forceinline__ float warp_sum(float v) {
#pragma unroll
    for (int m = 16; m; m >>= 1) v += __shfl_xor_sync(0xffffffffu, v, m);
    return v;
}

__device__ __forceinline__ void st_cluster_v4(const float* p, int rank, float4 v) {
    unsigned a = (unsigned)__cvta_generic_to_shared(p);
    unsigned r;
    asm("mapa.shared::cluster.u32 %0, %1, %2;" : "=r"(r) : "r"(a), "r"(rank));
    asm volatile("st.shared::cluster.v4.f32 [%0], {%1, %2, %3, %4};"
                 :: "r"(r), "f"(v.x), "f"(v.y), "f"(v.z), "f"(v.w) : "memory");
}

__device__ __forceinline__ void arrive_cluster(unsigned local_mbar, int rank) {
    unsigned r;
    asm("mapa.shared::cluster.u32 %0, %1, %2;" : "=r"(r) : "r"(local_mbar), "r"(rank));
    asm volatile("mbarrier.arrive.release.cluster.shared::cluster.b64 _, [%0];"
                 :: "r"(r) : "memory");
}

// SINGLE CHANGE vs R5: cta-scope acquire wait (production-macro pattern).
// Data was written remotely INTO our own smem; cta acquire suffices.
__device__ __forceinline__ void waitc(unsigned mbar) {
    asm volatile(
        "{\n\t"
        ".reg .pred P;\n\t"
        "WL%=:\n\t"
        "mbarrier.try_wait.parity.acquire.cta.shared::cta.b64 P, [%0], 0, 0x989680;\n\t"
        "@!P bra WL%=;\n\t"
        "}"
        :: "r"(mbar) : "memory");
}

__device__ __forceinline__ float dot8(float4 wa, float4 wb, float4 xa, float4 xb) {
    return wa.x*xa.x + wa.y*xa.y + wa.z*xa.z + wa.w*xa.w
         + wb.x*xb.x + wb.y*xb.y + wb.z*xb.z + wb.w*xb.w;
}

// ---------------------------------------------------------------------------
// feat: g_feat[t][0:128]  = elu(v0[t] @ W1v.T + b1v)   (warp-per-output)
//       g_feat[t][128:256]= elu(m0[t] @ W1m.T + b1m)
// ---------------------------------------------------------------------------
__global__ void feat_kernel(const float* __restrict__ v0, const float* __restrict__ m0,
                            const float* __restrict__ W1v, const float* __restrict__ b1v,
                            const float* __restrict__ W1m, const float* __restrict__ b1m)
{
    int t = blockIdx.x, by = blockIdx.y;
    int w = threadIdx.x >> 5, l = threadIdx.x & 31;
    if (by < 16) {
        int o = by * 8 + w;                    // 0..127
        const float* vr = v0 + t * 768;
        const float* wr = W1v + o * 768;
        float acc = 0.f;
#pragma unroll
        for (int c = 0; c < 6; c++) {
            float4 a = *(const float4*)(vr + c * 128 + 4 * l);
            float4 b = *(const float4*)(wr + c * 128 + 4 * l);
            acc += a.x*b.x + a.y*b.y + a.z*b.z + a.w*b.w;
        }
        acc = warp_sum(acc);
        if (l == 0) g_feat[t * 256 + o] = eluf(acc + b1v[o]);
    } else {
        int f = threadIdx.x;
        if (f < 128) {
            float acc = b1m[f] + m0[t * 2] * W1m[f * 2] + m0[t * 2 + 1] * W1m[f * 2 + 1];
            g_feat[t * 256 + 128 + f] = eluf(acc);
        }
    }
}

// ---------------------------------------------------------------------------
// pre2: g_pre[t][j] = Wih_low[j, :256] @ g_feat[t] + bih_low[j]
//                     + (bhh_low[j] for j<512)           (warp-per-output)
// ---------------------------------------------------------------------------
__global__ void pre2_kernel(const float* __restrict__ Wih_low,
                            const float* __restrict__ bih_low,
                            const float* __restrict__ bhh_low)
{
    int t = blockIdx.x;
    int w = threadIdx.x >> 5, l = threadIdx.x & 31;
    int o = blockIdx.y * 8 + w;                // 0..767
    const float* xr = g_feat + t * 256;
    const float* wr = Wih_low + o * 512;
    float4 a0 = *(const float4*)(xr + 4 * l);
    float4 a1 = *(const float4*)(xr + 128 + 4 * l);
    float4 b0 = *(const float4*)(wr + 4 * l);
    float4 b1 = *(const float4*)(wr + 128 + 4 * l);
    float acc = warp_sum(dot8(b0, b1, a0, a1));
    if (l == 0)
        g_pre[t * 768 + o] = acc + bih_low[o] + (o < 512 ? bhh_low[o] : 0.f);
}

// ---------------------------------------------------------------------------
// Recurrent kernel: persistent 16-CTA cluster, one hidden unit per warp.
// Smem: W_lh2 (= Wih_low[:,256:512]) + Wih_high. Regs: Whh_low, Whh_high.
// Exchange (R5 pattern): lane0 deposits h into 16-float gather buf;
// __syncthreads; warp0 lanes 0-15 fan out the CTA's 16 values as 4x v4
// DSMEM stores to rank l + one release-arrive each on the per-phase
// one-shot mbarrier (count=16). Consumers: cta-scope acquire try_wait.
// ---------------------------------------------------------------------------
__global__ void __launch_bounds__(THREADS, 1) gru_kernel(
    const float* __restrict__ Wih_low, const float* __restrict__ Whh_low,
    const float* __restrict__ bhh_low,
    const float* __restrict__ Wih_high, const float* __restrict__ Whh_high,
    const float* __restrict__ bih_high, const float* __restrict__ bhh_high)
{
    extern __shared__ float smem[];
    float* sW  = smem;                       // [NW][2 mats][3 rows][256]  = 24576 floats
    float* sH1 = smem + NW * 1536;           // [2][256] double-buffered
    float* sH2 = sH1 + 512;                  // [2][256]
    float* sG  = sH2 + 512;                  // [16] local gather (16B aligned)

    const int tid = threadIdx.x;
    const int w = tid >> 5, l = tid & 31;
    unsigned rank;
    asm("mov.u32 %0, %%cluster_ctarank;" : "=r"(rank));
    const int i = (int)rank * NW + w;        // global hidden index 0..255
    const int c0 = 4 * l, c1 = 128 + 4 * l;
    float* wb = sW + w * 1536;

    const unsigned sm_base = (unsigned)__cvta_generic_to_shared(smem);
    const unsigned mb0 = sm_base + (NW * 1536 + 512 + 512 + 16) * 4;  // mbar array base

    sH1[tid] = 0.f;
    sH2[tid] = 0.f;
    if (tid == 0) {
#pragma unroll 4
        for (int k = 0; k < NMBAR; k++)
            asm volatile("mbarrier.init.shared.b64 [%0], %1;"
                         :: "r"(mb0 + 8u * k), "r"(NCTA) : "memory");
    }

    const int j0 = i, j1 = 256 + i, j2 = 512 + i;
    const int jj[3] = { j0, j1, j2 };

    float4 wlh[3][2], whh[3][2];
#pragma unroll
    for (int g = 0; g < 3; g++) {
        int j = jj[g];
        *(float4*)(wb + g * 256 + c0)       = *(const float4*)(Wih_low + j * 512 + 256 + c0);
        *(float4*)(wb + g * 256 + c1)       = *(const float4*)(Wih_low + j * 512 + 256 + c1);
        *(float4*)(wb + 768 + g * 256 + c0) = *(const float4*)(Wih_high + j * 256 + c0);
        *(float4*)(wb + 768 + g * 256 + c1) = *(const float4*)(Wih_high + j * 256 + c1);
        wlh[g][0] = *(const float4*)(Whh_low + j * 256 + c0);
        wlh[g][1] = *(const float4*)(Whh_low + j * 256 + c1);
        whh[g][0] = *(const float4*)(Whh_high + j * 256 + c0);
        whh[g][1] = *(const float4*)(Whh_high + j * 256 + c1);
    }

    const float bLn = bhh_low[512 + i];                      // gh_n bias (low)
    const float cAr = bih_high[i] + bhh_high[i];             // high r: both biases fold
    const float cAz = bih_high[256 + i] + bhh_high[256 + i]; // high z
    const float cAn = bih_high[512 + i];                     // high n: gi bias
    const float cBn = bhh_high[512 + i];                     // high n: gh bias

    __syncthreads();
    // publish mbarrier inits + zeroed buffers cluster-wide (one-time)
    asm volatile("barrier.cluster.arrive.aligned;" ::: "memory");
    asm volatile("barrier.cluster.wait.aligned;" ::: "memory");

    float h1prev = 0.f, h2prev = 0.f;
    float Blr = 0.f, Blz = 0.f, Bln = 0.f;   // Whh_low @ h1(-1) = 0
    float pr = g_pre[j0], pz = g_pre[j1], pn = g_pre[j2];

    for (int t = 0; t < TT; t++) {
        const int p = t & 1;
        // ================= phase 1: low GRU (produce h1(t)) ==========
        if (t > 0) waitc(mb0 + 8u * (2 * t - 1));     // h2(t-1) arrivals
        float4 h2a = *(const float4*)(sH2 + (p ^ 1) * 256 + c0);
        float4 h2b = *(const float4*)(sH2 + (p ^ 1) * 256 + c1);
        float A0, A1, A2v;
        {
            float4 wa0 = *(const float4*)(wb + 0 * 256 + c0);
            float4 wb0 = *(const float4*)(wb + 0 * 256 + c1);
            float4 wa1 = *(const float4*)(wb + 1 * 256 + c0);
            float4 wb1 = *(const float4*)(wb + 1 * 256 + c1);
            float4 wa2 = *(const float4*)(wb + 2 * 256 + c0);
            float4 wb2 = *(const float4*)(wb + 2 * 256 + c1);
            A0 = dot8(wa0, wb0, h2a, h2b);
            A1 = dot8(wa1, wb1, h2a, h2b);
            A2v = dot8(wa2, wb2, h2a, h2b);
        }
        float Ar = warp_sum(A0), Az = warp_sum(A1), An = warp_sum(A2v);
        float r = sigmfast(pr + Ar + Blr);
        float z = sigmfast(pz + Az + Blz);
        float n = tanhfast(pn + An + r * (Bln + bLn));
        float h1n = (1.f - z) * n + z * h1prev;
        h1prev = h1n;

        if (l == 0) sG[w] = h1n;
        if (l == 16) g_lout[t * 256 + i] = h1n;       // off critical path
        __syncthreads();
        if (w == 0 && l < NCTA) {
            const float4* gg = (const float4*)sG;
            float4 g0 = gg[0], g1 = gg[1], g2 = gg[2], g3 = gg[3];
            float* dst = sH1 + p * 256 + (int)rank * 16;
            st_cluster_v4(dst + 0,  l, g0);
            st_cluster_v4(dst + 4,  l, g1);
            st_cluster_v4(dst + 8,  l, g2);
            st_cluster_v4(dst + 12, l, g3);
            arrive_cluster(mb0 + 8u * (2 * t), l);
        }
        // hidden work (overlaps DSMEM transit): B_high = Whh_high @ h2(t-1)
        float Bhr = warp_sum(dot8(whh[0][0], whh[0][1], h2a, h2b));
        float Bhz = warp_sum(dot8(whh[1][0], whh[1][1], h2a, h2b));
        float Bhn = warp_sum(dot8(whh[2][0], whh[2][1], h2a, h2b));

        waitc(mb0 + 8u * (2 * t));                    // h1(t) arrivals
        float4 h1a = *(const float4*)(sH1 + p * 256 + c0);
        float4 h1b = *(const float4*)(sH1 + p * 256 + c1);

        // ================= phase 2: high GRU (produce h2(t)) =========
        float G0, G1, G2;
        {
            float4 wa0 = *(const float4*)(wb + 768 + 0 * 256 + c0);
            float4 wb0 = *(const float4*)(wb + 768 + 0 * 256 + c1);
            float4 wa1 = *(const float4*)(wb + 768 + 1 * 256 + c0);
            float4 wb1 = *(const float4*)(wb + 768 + 1 * 256 + c1);
            float4 wa2 = *(const float4*)(wb + 768 + 2 * 256 + c0);
            float4 wb2 = *(const float4*)(wb + 768 + 2 * 256 + c1);
            G0 = dot8(wa0, wb0, h1a, h1b);
            G1 = dot8(wa1, wb1, h1a, h1b);
            G2 = dot8(wa2, wb2, h1a, h1b);
        }
        float A2r = warp_sum(G0), A2z = warp_sum(G1), A2n = warp_sum(G2);
        float r2 = sigmfast(cAr + A2r + Bhr);
        float z2 = sigmfast(cAz + A2z + Bhz);
        float n2 = tanhfast(cAn + A2n + r2 * (Bhn + cBn));
        float h2n = (1.f - z2) * n2 + z2 * h2prev;
        h2prev = h2n;

        if (l == 0) sG[w] = h2n;
        __syncthreads();
        if (w == 0 && l < NCTA) {
            const float4* gg = (const float4*)sG;
            float4 g0 = gg[0], g1 = gg[1], g2 = gg[2], g3 = gg[3];
            float* dst = sH2 + p * 256 + (int)rank * 16;
            st_cluster_v4(dst + 0,  l, g0);
            st_cluster_v4(dst + 4,  l, g1);
            st_cluster_v4(dst + 8,  l, g2);
            st_cluster_v4(dst + 12, l, g3);
            arrive_cluster(mb0 + 8u * (2 * t + 1), l);
        }
        // hidden work: next step's B_low = Whh_low @ h1(t); prefetch pre
        Blr = warp_sum(dot8(wlh[0][0], wlh[0][1], h1a, h1b));
        Blz = warp_sum(dot8(wlh[1][0], wlh[1][1], h1a, h1b));
        Bln = warp_sum(dot8(wlh[2][0], wlh[2][1], h1a, h1b));
        if (t + 1 < TT) {
            pr = __ldg(g_pre + (t + 1) * 768 + j0);
            pz = __ldg(g_pre + (t + 1) * 768 + j1);
            pn = __ldg(g_pre + (t + 1) * 768 + j2);
        }
    }
    // trailing cluster sync: no CTA exits while peers' DSMEM ops may target it
    asm volatile("barrier.cluster.arrive.aligned;" ::: "memory");
    asm volatile("barrier.cluster.wait.aligned;" ::: "memory");
}

// ---------------------------------------------------------------------------
// Post-kernel (warp-per-output):
//   v_n[t][o] = sigmoid(elu(h1[t][0:128]) . W2v[o] + b2v[o])
//   m_n[t][o] = tanh   (elu(h1[t][128:256]) . W2m[o] + b2m[o])
// ---------------------------------------------------------------------------
__global__ void post_kernel(const float* __restrict__ W2v, const float* __restrict__ b2v,
                            const float* __restrict__ W2m, const float* __restrict__ b2m,
                            float* __restrict__ out)
{
    int t = blockIdx.x, by = blockIdx.y;
    int w = threadIdx.x >> 5, l = threadIdx.x & 31;
    if (by < 12) {
        float4 h = *(const float4*)(g_lout + t * 256 + 4 * l);
        h.x = eluf(h.x); h.y = eluf(h.y); h.z = eluf(h.z); h.w = eluf(h.w);
#pragma unroll
        for (int q = 0; q < 8; q++) {
            int o = by * 64 + w * 8 + q;
            float4 b = *(const float4*)(W2v + o * 128 + 4 * l);
            float acc = warp_sum(h.x*b.x + h.y*b.y + h.z*b.z + h.w*b.w);
            if (l == 0) out[t * 768 + o] = sigm(acc + b2v[o]);
        }
    } else if (w < 2) {
        float4 h = *(const float4*)(g_lout + t * 256 + 128 + 4 * l);
        h.x = eluf(h.x); h.y = eluf(h.y); h.z = eluf(h.z); h.w = eluf(h.w);
        float4 b = *(const float4*)(W2m + w * 128 + 4 * l);
        float acc = warp_sum(h.x*b.x + h.y*b.y + h.z*b.z + h.w*b.w);
        if (l == 0) out[TT * 768 + t * 2 + w] = tanhf(acc + b2m[w]);
    }
}

// ---------------------------------------------------------------------------
extern "C" void kernel_launch(void* const* d_in, const int* in_sizes, int n_in,
                              void* d_out, int out_size) {
    const float* v0       = (const float*)d_in[0];
    const float* m0       = (const float*)d_in[1];
    const float* W1v      = (const float*)d_in[2];
    const float* b1v      = (const float*)d_in[3];
    const float* W1m      = (const float*)d_in[4];
    const float* b1m      = (const float*)d_in[5];
    const float* Wih_low  = (const float*)d_in[6];
    const float* Whh_low  = (const float*)d_in[7];
    const float* bih_low  = (const float*)d_in[8];
    const float* bhh_low  = (const float*)d_in[9];
    const float* Wih_high = (const float*)d_in[10];
    const float* Whh_high = (const float*)d_in[11];
    const float* bih_high = (const float*)d_in[12];
    const float* bhh_high = (const float*)d_in[13];
    const float* W2v      = (const float*)d_in[14];
    const float* b2v      = (const float*)d_in[15];
    const float* W2m      = (const float*)d_in[16];
    const float* b2m      = (const float*)d_in[17];
    float* out = (float*)d_out;

    feat_kernel<<<dim3(TT, 17), 256>>>(v0, m0, W1v, b1v, W1m, b1m);
    pre2_kernel<<<dim3(TT, 96), 256>>>(Wih_low, bih_low, bhh_low);

    // smem: weights 24576 + h1 512 + h2 512 + gather 16 floats, + 100 mbars
    const int SMEM = (NW * 1536 + 512 + 512 + 16) * (int)sizeof(float) + NMBAR * 8;
    cudaFuncSetAttribute(gru_kernel, cudaFuncAttributeMaxDynamicSharedMemorySize, SMEM);
    cudaFuncSetAttribute(gru_kernel, cudaFuncAttributeNonPortableClusterSizeAllowed, 1);

    cudaLaunchConfig_t cfg = {};
    cfg.gridDim = dim3(NCTA, 1, 1);
    cfg.blockDim = dim3(THREADS, 1, 1);
    cfg.dynamicSmemBytes = SMEM;
    cfg.stream = 0;
    cudaLaunchAttribute attr[1];
    attr[0].id = cudaLaunchAttributeClusterDimension;
    attr[0].val.clusterDim.x = NCTA;
    attr[0].val.clusterDim.y = 1;
    attr[0].val.clusterDim.z = 1;
    cfg.attrs = attr;
    cfg.numAttrs = 1;
    cudaLaunchKernelEx(&cfg, gru_kernel, Wih_low, Whh_low, bhh_low,
                       Wih_high, Whh_high, bih_high, bhh_high);

    post_kernel<<<dim3(TT, 13), 256>>>(W2v, b2v, W2m, b2m, out);
}

// round 10
// speedup vs baseline: 1.7753x; 1.3788x over previous
#include <cuda_runtime.h>
#include <math.h>

#define TT 50
#define HH 256
#define NCTA 16
#define NW 16
#define THREADS 512
#define NMBAR (2 * TT)
// tx bytes expected per phase per CTA: 16 source CTAs x 4 st.async x 16B
#define PHASE_TX (NCTA * 64)

// scratch (no allocations allowed)
__device__ float g_feat[TT * 256];
__device__ float g_pre[TT * 768];
__device__ float g_lout[TT * HH];

__device__ __forceinline__ float eluf(float x) { return x > 0.f ? x : expm1f(x); }
__device__ __forceinline__ float sigm(float x) { return 1.f / (1.f + expf(-x)); }
// fast versions (recurrence only; ~1e-6 rel err, margin is 1e-3)
__device__ __forceinline__ float sigmfast(float x) {
    return __fdividef(1.f, 1.f + __expf(-x));
}
__device__ __forceinline__ float tanhfast(float x) {
    return __fdividef(2.f, 1.f + __expf(-2.f * x)) - 1.f;
}

__device__ __forceinline__ float warp_sum(float v) {
#pragma unroll
    for (int m = 16; m; m >>= 1) v += __shfl_xor_sync(0xffffffffu, v, m);
    return v;
}

// Fused data+signal: async remote store that credits the destination CTA's
// mbarrier transaction count on delivery (TMA-style completion mechanism).
__device__ __forceinline__ void st_async_v4(const float* p, unsigned mbar_local,
                                            int rank, float4 v) {
    unsigned a = (unsigned)__cvta_generic_to_shared(p);
    unsigned ra, rb;
    asm("mapa.shared::cluster.u32 %0, %1, %2;" : "=r"(ra) : "r"(a), "r"(rank));
    asm("mapa.shared::cluster.u32 %0, %1, %2;" : "=r"(rb) : "r"(mbar_local), "r"(rank));
    asm volatile(
        "st.async.shared::cluster.mbarrier::complete_tx::bytes.v4.f32 "
        "[%0], {%1, %2, %3, %4}, [%5];"
        :: "r"(ra), "f"(v.x), "f"(v.y), "f"(v.z), "f"(v.w), "r"(rb) : "memory");
}

// cta-scope acquire wait (production-macro pattern): data lands in OUR smem.
__device__ __forceinline__ void waitc(unsigned mbar) {
    asm volatile(
        "{\n\t"
        ".reg .pred P;\n\t"
        "WL%=:\n\t"
        "mbarrier.try_wait.parity.acquire.cta.shared::cta.b64 P, [%0], 0, 0x989680;\n\t"
        "@!P bra WL%=;\n\t"
        "}"
        :: "r"(mbar) : "memory");
}

__device__ __forceinline__ float dot8(float4 wa, float4 wb, float4 xa, float4 xb) {
    return wa.x*xa.x + wa.y*xa.y + wa.z*xa.z + wa.w*xa.w
         + wb.x*xb.x + wb.y*xb.y + wb.z*xb.z + wb.w*xb.w;
}

// ---------------------------------------------------------------------------
// feat: g_feat[t][0:128]  = elu(v0[t] @ W1v.T + b1v)   (warp-per-output)
//       g_feat[t][128:256]= elu(m0[t] @ W1m.T + b1m)
// ---------------------------------------------------------------------------
__global__ void feat_kernel(const float* __restrict__ v0, const float* __restrict__ m0,
                            const float* __restrict__ W1v, const float* __restrict__ b1v,
                            const float* __restrict__ W1m, const float* __restrict__ b1m)
{
    int t = blockIdx.x, by = blockIdx.y;
    int w = threadIdx.x >> 5, l = threadIdx.x & 31;
    if (by < 16) {
        int o = by * 8 + w;                    // 0..127
        const float* vr = v0 + t * 768;
        const float* wr = W1v + o * 768;
        float acc = 0.f;
#pragma unroll
        for (int c = 0; c < 6; c++) {
            float4 a = *(const float4*)(vr + c * 128 + 4 * l);
            float4 b = *(const float4*)(wr + c * 128 + 4 * l);
            acc += a.x*b.x + a.y*b.y + a.z*b.z + a.w*b.w;
        }
        acc = warp_sum(acc);
        if (l == 0) g_feat[t * 256 + o] = eluf(acc + b1v[o]);
    } else {
        int f = threadIdx.x;
        if (f < 128) {
            float acc = b1m[f] + m0[t * 2] * W1m[f * 2] + m0[t * 2 + 1] * W1m[f * 2 + 1];
            g_feat[t * 256 + 128 + f] = eluf(acc);
        }
    }
}

// ---------------------------------------------------------------------------
// pre2: g_pre[t][j] = Wih_low[j, :256] @ g_feat[t] + bih_low[j]
//                     + (bhh_low[j] for j<512)           (warp-per-output)
// ---------------------------------------------------------------------------
__global__ void pre2_kernel(const float* __restrict__ Wih_low,
                            const float* __restrict__ bih_low,
                            const float* __restrict__ bhh_low)
{
    int t = blockIdx.x;
    int w = threadIdx.x >> 5, l = threadIdx.x & 31;
    int o = blockIdx.y * 8 + w;                // 0..767
    const float* xr = g_feat + t * 256;
    const float* wr = Wih_low + o * 512;
    float4 a0 = *(const float4*)(xr + 4 * l);
    float4 a1 = *(const float4*)(xr + 128 + 4 * l);
    float4 b0 = *(const float4*)(wr + 4 * l);
    float4 b1 = *(const float4*)(wr + 128 + 4 * l);
    float acc = warp_sum(dot8(b0, b1, a0, a1));
    if (l == 0)
        g_pre[t * 768 + o] = acc + bih_low[o] + (o < 512 ? bhh_low[o] : 0.f);
}

// ---------------------------------------------------------------------------
// Recurrent kernel: persistent 16-CTA cluster, one hidden unit per warp.
// Smem: W_lh2 (= Wih_low[:,256:512]) + Wih_high. Regs: Whh_low, Whh_high.
// Exchange: lane0 deposits h into 16-float gather buf; __syncthreads;
// warp0 lanes 0-15 ship 4x v4 st.async (data + tx-credit fused) to rank l's
// per-phase one-shot mbarrier. mbar: init count=1, arrive.expect_tx(1024B)
// at kernel start. Consumers: cta-scope acquire try_wait, parity 0.
// ---------------------------------------------------------------------------
__global__ void __launch_bounds__(THREADS, 1) gru_kernel(
    const float* __restrict__ Wih_low, const float* __restrict__ Whh_low,
    const float* __restrict__ bhh_low,
    const float* __restrict__ Wih_high, const float* __restrict__ Whh_high,
    const float* __restrict__ bih_high, const float* __restrict__ bhh_high)
{
    extern __shared__ float smem[];
    float* sW  = smem;                       // [NW][2 mats][3 rows][256]  = 24576 floats
    float* sH1 = smem + NW * 1536;           // [2][256] double-buffered
    float* sH2 = sH1 + 512;                  // [2][256]
    float* sG  = sH2 + 512;                  // [16] local gather (16B aligned)

    const int tid = threadIdx.x;
    const int w = tid >> 5, l = tid & 31;
    unsigned rank;
    asm("mov.u32 %0, %%cluster_ctarank;" : "=r"(rank));
    const int i = (int)rank * NW + w;        // global hidden index 0..255
    const int c0 = 4 * l, c1 = 128 + 4 * l;
    float* wb = sW + w * 1536;

    const unsigned sm_base = (unsigned)__cvta_generic_to_shared(smem);
    const unsigned mb0 = sm_base + (NW * 1536 + 512 + 512 + 16) * 4;  // mbar array base

    sH1[tid] = 0.f;
    sH2[tid] = 0.f;
    if (tid == 0) {
        for (int k = 0; k < NMBAR; k++)
            asm volatile("mbarrier.init.shared.b64 [%0], %1;"
                         :: "r"(mb0 + 8u * k), "r"(1) : "memory");
        // consume the single arrival and post the tx expectation for every
        // phase up front (tx-count is signed: early credits are legal).
        for (int k = 0; k < NMBAR; k++)
            asm volatile("mbarrier.arrive.expect_tx.shared.b64 _, [%0], %1;"
                         :: "r"(mb0 + 8u * k), "r"(PHASE_TX) : "memory");
    }

    const int j0 = i, j1 = 256 + i, j2 = 512 + i;
    const int jj[3] = { j0, j1, j2 };

    float4 wlh[3][2], whh[3][2];
#pragma unroll
    for (int g = 0; g < 3; g++) {
        int j = jj[g];
        *(float4*)(wb + g * 256 + c0)       = *(const float4*)(Wih_low + j * 512 + 256 + c0);
        *(float4*)(wb + g * 256 + c1)       = *(const float4*)(Wih_low + j * 512 + 256 + c1);
        *(float4*)(wb + 768 + g * 256 + c0) = *(const float4*)(Wih_high + j * 256 + c0);
        *(float4*)(wb + 768 + g * 256 + c1) = *(const float4*)(Wih_high + j * 256 + c1);
        wlh[g][0] = *(const float4*)(Whh_low + j * 256 + c0);
        wlh[g][1] = *(const float4*)(Whh_low + j * 256 + c1);
        whh[g][0] = *(const float4*)(Whh_high + j * 256 + c0);
        whh[g][1] = *(const float4*)(Whh_high + j * 256 + c1);
    }

    const float bLn = bhh_low[512 + i];                      // gh_n bias (low)
    const float cAr = bih_high[i] + bhh_high[i];             // high r: both biases fold
    const float cAz = bih_high[256 + i] + bhh_high[256 + i]; // high z
    const float cAn = bih_high[512 + i];                     // high n: gi bias
    const float cBn = bhh_high[512 + i];                     // high n: gh bias

    __syncthreads();
    // publish mbarrier inits + zeroed buffers cluster-wide (one-time)
    asm volatile("barrier.cluster.arrive.aligned;" ::: "memory");
    asm volatile("barrier.cluster.wait.aligned;" ::: "memory");

    float h1prev = 0.f, h2prev = 0.f;
    float Blr = 0.f, Blz = 0.f, Bln = 0.f;   // Whh_low @ h1(-1) = 0
    float pr = g_pre[j0], pz = g_pre[j1], pn = g_pre[j2];

    for (int t = 0; t < TT; t++) {
        const int p = t & 1;
        // ================= phase 1: low GRU (produce h1(t)) ==========
        if (t > 0) waitc(mb0 + 8u * (2 * t - 1));     // h2(t-1) delivery
        float4 h2a = *(const float4*)(sH2 + (p ^ 1) * 256 + c0);
        float4 h2b = *(const float4*)(sH2 + (p ^ 1) * 256 + c1);
        float A0, A1, A2v;
        {
            float4 wa0 = *(const float4*)(wb + 0 * 256 + c0);
            float4 wb0 = *(const float4*)(wb + 0 * 256 + c1);
            float4 wa1 = *(const float4*)(wb + 1 * 256 + c0);
            float4 wb1 = *(const float4*)(wb + 1 * 256 + c1);
            float4 wa2 = *(const float4*)(wb + 2 * 256 + c0);
            float4 wb2 = *(const float4*)(wb + 2 * 256 + c1);
            A0 = dot8(wa0, wb0, h2a, h2b);
            A1 = dot8(wa1, wb1, h2a, h2b);
            A2v = dot8(wa2, wb2, h2a, h2b);
        }
        float Ar = warp_sum(A0), Az = warp_sum(A1), An = warp_sum(A2v);
        float r = sigmfast(pr + Ar + Blr);
        float z = sigmfast(pz + Az + Blz);
        float n = tanhfast(pn + An + r * (Bln + bLn));
        float h1n = (1.f - z) * n + z * h1prev;
        h1prev = h1n;

        if (l == 0) sG[w] = h1n;
        if (l == 16) g_lout[t * 256 + i] = h1n;       // off critical path
        __syncthreads();
        if (w == 0 && l < NCTA) {
            const float4* gg = (const float4*)sG;
            float4 g0 = gg[0], g1 = gg[1], g2 = gg[2], g3 = gg[3];
            float* dst = sH1 + p * 256 + (int)rank * 16;
            unsigned mb = mb0 + 8u * (2 * t);
            st_async_v4(dst + 0,  mb, l, g0);
            st_async_v4(dst + 4,  mb, l, g1);
            st_async_v4(dst + 8,  mb, l, g2);
            st_async_v4(dst + 12, mb, l, g3);
        }
        // hidden work (overlaps fabric transit): B_high = Whh_high @ h2(t-1)
        float Bhr = warp_sum(dot8(whh[0][0], whh[0][1], h2a, h2b));
        float Bhz = warp_sum(dot8(whh[1][0], whh[1][1], h2a, h2b));
        float Bhn = warp_sum(dot8(whh[2][0], whh[2][1], h2a, h2b));

        waitc(mb0 + 8u * (2 * t));                    // h1(t) delivery
        float4 h1a = *(const float4*)(sH1 + p * 256 + c0);
        float4 h1b = *(const float4*)(sH1 + p * 256 + c1);

        // ================= phase 2: high GRU (produce h2(t)) =========
        float G0, G1, G2;
        {
            float4 wa0 = *(const float4*)(wb + 768 + 0 * 256 + c0);
            float4 wb0 = *(const float4*)(wb + 768 + 0 * 256 + c1);
            float4 wa1 = *(const float4*)(wb + 768 + 1 * 256 + c0);
            float4 wb1 = *(const float4*)(wb + 768 + 1 * 256 + c1);
            float4 wa2 = *(const float4*)(wb + 768 + 2 * 256 + c0);
            float4 wb2 = *(const float4*)(wb + 768 + 2 * 256 + c1);
            G0 = dot8(wa0, wb0, h1a, h1b);
            G1 = dot8(wa1, wb1, h1a, h1b);
            G2 = dot8(wa2, wb2, h1a, h1b);
        }
        float A2r = warp_sum(G0), A2z = warp_sum(G1), A2n = warp_sum(G2);
        float r2 = sigmfast(cAr + A2r + Bhr);
        float z2 = sigmfast(cAz + A2z + Bhz);
        float n2 = tanhfast(cAn + A2n + r2 * (Bhn + cBn));
        float h2n = (1.f - z2) * n2 + z2 * h2prev;
        h2prev = h2n;

        if (l == 0) sG[w] = h2n;
        __syncthreads();
        if (w == 0 && l < NCTA) {
            const float4* gg = (const float4*)sG;
            float4 g0 = gg[0], g1 = gg[1], g2 = gg[2], g3 = gg[3];
            float* dst = sH2 + p * 256 + (int)rank * 16;
            unsigned mb = mb0 + 8u * (2 * t + 1);
            st_async_v4(dst + 0,  mb, l, g0);
            st_async_v4(dst + 4,  mb, l, g1);
            st_async_v4(dst + 8,  mb, l, g2);
            st_async_v4(dst + 12, mb, l, g3);
        }
        // hidden work: next step's B_low = Whh_low @ h1(t); prefetch pre
        Blr = warp_sum(dot8(wlh[0][0], wlh[0][1], h1a, h1b));
        Blz = warp_sum(dot8(wlh[1][0], wlh[1][1], h1a, h1b));
        Bln = warp_sum(dot8(wlh[2][0], wlh[2][1], h1a, h1b));
        if (t + 1 < TT) {
            pr = __ldg(g_pre + (t + 1) * 768 + j0);
            pz = __ldg(g_pre + (t + 1) * 768 + j1);
            pn = __ldg(g_pre + (t + 1) * 768 + j2);
        }
    }
    // trailing cluster sync: no CTA exits while peers' DSMEM ops may target it
    asm volatile("barrier.cluster.arrive.aligned;" ::: "memory");
    asm volatile("barrier.cluster.wait.aligned;" ::: "memory");
}

// ---------------------------------------------------------------------------
// Post-kernel (warp-per-output):
//   v_n[t][o] = sigmoid(elu(h1[t][0:128]) . W2v[o] + b2v[o])
//   m_n[t][o] = tanh   (elu(h1[t][128:256]) . W2m[o] + b2m[o])
// ---------------------------------------------------------------------------
__global__ void post_kernel(const float* __restrict__ W2v, const float* __restrict__ b2v,
                            const float* __restrict__ W2m, const float* __restrict__ b2m,
                            float* __restrict__ out)
{
    int t = blockIdx.x, by = blockIdx.y;
    int w = threadIdx.x >> 5, l = threadIdx.x & 31;
    if (by < 12) {
        float4 h = *(const float4*)(g_lout + t * 256 + 4 * l);
        h.x = eluf(h.x); h.y = eluf(h.y); h.z = eluf(h.z); h.w = eluf(h.w);
#pragma unroll
        for (int q = 0; q < 8; q++) {
            int o = by * 64 + w * 8 + q;
            float4 b = *(const float4*)(W2v + o * 128 + 4 * l);
            float acc = warp_sum(h.x*b.x + h.y*b.y + h.z*b.z + h.w*b.w);
            if (l == 0) out[t * 768 + o] = sigm(acc + b2v[o]);
        }
    } else if (w < 2) {
        float4 h = *(const float4*)(g_lout + t * 256 + 128 + 4 * l);
        h.x = eluf(h.x); h.y = eluf(h.y); h.z = eluf(h.z); h.w = eluf(h.w);
        float4 b = *(const float4*)(W2m + w * 128 + 4 * l);
        float acc = warp_sum(h.x*b.x + h.y*b.y + h.z*b.z + h.w*b.w);
        if (l == 0) out[TT * 768 + t * 2 + w] = tanhf(acc + b2m[w]);
    }
}

// ---------------------------------------------------------------------------
extern "C" void kernel_launch(void* const* d_in, const int* in_sizes, int n_in,
                              void* d_out, int out_size) {
    const float* v0       = (const float*)d_in[0];
    const float* m0       = (const float*)d_in[1];
    const float* W1v      = (const float*)d_in[2];
    const float* b1v      = (const float*)d_in[3];
    const float* W1m      = (const float*)d_in[4];
    const float* b1m      = (const float*)d_in[5];
    const float* Wih_low  = (const float*)d_in[6];
    const float* Whh_low  = (const float*)d_in[7];
    const float* bih_low  = (const float*)d_in[8];
    const float* bhh_low  = (const float*)d_in[9];
    const float* Wih_high = (const float*)d_in[10];
    const float* Whh_high = (const float*)d_in[11];
    const float* bih_high = (const float*)d_in[12];
    const float* bhh_high = (const float*)d_in[13];
    const float* W2v      = (const float*)d_in[14];
    const float* b2v      = (const float*)d_in[15];
    const float* W2m      = (const float*)d_in[16];
    const float* b2m      = (const float*)d_in[17];
    float* out = (float*)d_out;

    feat_kernel<<<dim3(TT, 17), 256>>>(v0, m0, W1v, b1v, W1m, b1m);
    pre2_kernel<<<dim3(TT, 96), 256>>>(Wih_low, bih_low, bhh_low);

    // smem: weights 24576 + h1 512 + h2 512 + gather 16 floats, + 100 mbars
    const int SMEM = (NW * 1536 + 512 + 512 + 16) * (int)sizeof(float) + NMBAR * 8;
    cudaFuncSetAttribute(gru_kernel, cudaFuncAttributeMaxDynamicSharedMemorySize, SMEM);
    cudaFuncSetAttribute(gru_kernel, cudaFuncAttributeNonPortableClusterSizeAllowed, 1);

    cudaLaunchConfig_t cfg = {};
    cfg.gridDim = dim3(NCTA, 1, 1);
    cfg.blockDim = dim3(THREADS, 1, 1);
    cfg.dynamicSmemBytes = SMEM;
    cfg.stream = 0;
    cudaLaunchAttribute attr[1];
    attr[0].id = cudaLaunchAttributeClusterDimension;
    attr[0].val.clusterDim.x = NCTA;
    attr[0].val.clusterDim.y = 1;
    attr[0].val.clusterDim.z = 1;
    cfg.attrs = attr;
    cfg.numAttrs = 1;
    cudaLaunchKernelEx(&cfg, gru_kernel, Wih_low, Whh_low, bhh_low,
                       Wih_high, Whh_high, bih_high, bhh_high);

    post_kernel<<<dim3(TT, 13), 256>>>(W2v, b2v, W2m, b2m, out);
}